// round 7
// baseline (speedup 1.0000x reference)
#include <cuda_runtime.h>
#include <cuda_bf16.h>
#include <math.h>
#include <stdint.h>

#define CC    128          // channels
#define HHID  512          // expert hidden dim
#define EE    8            // routed experts
#define BB    8            // batch
#define HHW   9216         // 96*96
#define NTOK  73728        // BB*HHW
#define NOUT  (NTOK*CC)
#define TT    64           // tokens per tile (GEMM M)
#define HC    64           // hidden chunk
#define NCH   (HHID/HC)    // 8 chunks
#define NE1   (EE+1)
#define W1TOT (NE1*HHID*CC)

#define LDA   272          // row stride bytes for K=128 tiles (A, W1)
#define LDH   144          // row stride bytes for K=64 tiles (H, W2)
#define A_LO  17408        // 64*272
#define W_LO  18432        // 128*144 (covers W1 64*272=17408 too)
#define H_LO  9216         // 64*144

// ---- shared memory layout (bytes) ----
#define SM_TK    0
#define SM_TW    256
#define SM_BS    512
#define SM_A     1024
#define SM_W     (SM_A + 2*A_LO)     // 35840
#define SM_H     (SM_W + 2*W_LO)     // 72704
#define SM_TOTAL (SM_H + 2*H_LO)     // 91136

// ---- device scratch ----
__device__ __nv_bfloat16 g_xhi[(size_t)NTOK*CC];
__device__ __nv_bfloat16 g_xlo[(size_t)NTOK*CC];
__device__ __nv_bfloat16 g_w1hi[W1TOT], g_w1lo[W1TOT];
__device__ __nv_bfloat16 g_w2hi[W1TOT], g_w2lo[W1TOT];
__device__ int   g_tok[EE*NTOK];
__device__ float g_wt[EE*NTOK];
__device__ int   g_cnt[EE];
__device__ float g_probsum[EE];
__device__ int   g_loadsum[EE];

__device__ __forceinline__ float gelu_exact(float v) {
    return 0.5f * v * (1.0f + erff(v * 0.70710678118654752440f));
}
__device__ __forceinline__ uint32_t smem_u32(const void* p) {
    uint32_t a;
    asm("{ .reg .u64 t; cvta.to.shared.u64 t, %1; cvt.u32.u64 %0, t; }" : "=r"(a) : "l"(p));
    return a;
}
#define CP16(s, g)   asm volatile("cp.async.cg.shared.global [%0], [%1], 16;" :: "r"(s), "l"(g) : "memory")
#define CP_COMMIT()  asm volatile("cp.async.commit_group;" ::: "memory")
#define CP_WAIT0()   asm volatile("cp.async.wait_group 0;" ::: "memory")
#define LDM_X4(r0, r1, r2, r3, a) \
    asm volatile("ldmatrix.sync.aligned.m8n8.x4.shared.b16 {%0,%1,%2,%3}, [%4];" \
        : "=r"(r0), "=r"(r1), "=r"(r2), "=r"(r3) : "r"(a))

__device__ __forceinline__ void mma16816(float* d, const uint32_t* a, const uint32_t* b) {
    asm volatile("mma.sync.aligned.m16n8k16.row.col.f32.bf16.bf16.f32 "
        "{%0,%1,%2,%3}, {%4,%5,%6,%7}, {%8,%9}, {%0,%1,%2,%3};"
        : "+f"(d[0]), "+f"(d[1]), "+f"(d[2]), "+f"(d[3])
        : "r"(a[0]), "r"(a[1]), "r"(a[2]), "r"(a[3]), "r"(b[0]), "r"(b[1]));
}

// GEMM1 chunk: M64 (A tile K=128, LDA) x N64 (W1 rows, LDA). Warp tile 32x16.
__device__ __forceinline__ void gemm1_chunk(uint32_t smb, float acc[2][2][4],
                                            int lid, int wm, int wn) {
    int a_r  = (lid & 7) + ((lid >> 3) & 1) * 8;
    int a_ko = ((lid >> 4) & 1) * 16;
    int b_n  = (lid & 7) + ((lid >> 4) & 1) * 8;
    int b_ko = ((lid >> 3) & 1) * 16;
    uint32_t aBase = smb + SM_A + (uint32_t)(wm * 32 + a_r) * LDA + a_ko;
    uint32_t bBase = smb + SM_W + (uint32_t)(wn * 16 + b_n) * LDA + b_ko;
    #pragma unroll 2
    for (int k0 = 0; k0 < 8; k0++) {
        uint32_t kb = k0 * 32;
        uint32_t ah[2][4], al[2][4];
        #pragma unroll
        for (int mt = 0; mt < 2; mt++) {
            uint32_t ad = aBase + (uint32_t)(mt * 16) * LDA + kb;
            LDM_X4(ah[mt][0], ah[mt][1], ah[mt][2], ah[mt][3], ad);
            LDM_X4(al[mt][0], al[mt][1], al[mt][2], al[mt][3], ad + A_LO);
        }
        uint32_t bd = bBase + kb;
        uint32_t bh[4], bl[4];
        LDM_X4(bh[0], bh[1], bh[2], bh[3], bd);
        LDM_X4(bl[0], bl[1], bl[2], bl[3], bd + W_LO);
        #pragma unroll
        for (int g = 0; g < 2; g++)
            #pragma unroll
            for (int mt = 0; mt < 2; mt++) {
                mma16816(acc[mt][g], ah[mt], bh + 2 * g);
                mma16816(acc[mt][g], ah[mt], bl + 2 * g);
                mma16816(acc[mt][g], al[mt], bh + 2 * g);
            }
    }
}

// GEMM2 chunk: M64 (H tile K=64, LDH) x N128 (W2 rows, LDH). Warp tile 32x32.
__device__ __forceinline__ void gemm2_chunk(uint32_t smb, float acc[2][4][4],
                                            int lid, int wm, int wn) {
    int a_r  = (lid & 7) + ((lid >> 3) & 1) * 8;
    int a_ko = ((lid >> 4) & 1) * 16;
    int b_n  = (lid & 7) + ((lid >> 4) & 1) * 8;
    int b_ko = ((lid >> 3) & 1) * 16;
    uint32_t aBase = smb + SM_H + (uint32_t)(wm * 32 + a_r) * LDH + a_ko;
    uint32_t bBase = smb + SM_W + (uint32_t)(wn * 32 + b_n) * LDH + b_ko;
    #pragma unroll
    for (int k0 = 0; k0 < 4; k0++) {
        uint32_t kb = k0 * 32;
        uint32_t ah[2][4], al[2][4];
        #pragma unroll
        for (int mt = 0; mt < 2; mt++) {
            uint32_t ad = aBase + (uint32_t)(mt * 16) * LDH + kb;
            LDM_X4(ah[mt][0], ah[mt][1], ah[mt][2], ah[mt][3], ad);
            LDM_X4(al[mt][0], al[mt][1], al[mt][2], al[mt][3], ad + H_LO);
        }
        #pragma unroll
        for (int ntp = 0; ntp < 2; ntp++) {
            uint32_t bd = bBase + (uint32_t)(ntp * 16) * LDH + kb;
            uint32_t bh[4], bl[4];
            LDM_X4(bh[0], bh[1], bh[2], bh[3], bd);
            LDM_X4(bl[0], bl[1], bl[2], bl[3], bd + W_LO);
            #pragma unroll
            for (int g = 0; g < 2; g++) {
                int nt = ntp * 2 + g;
                #pragma unroll
                for (int mt = 0; mt < 2; mt++) {
                    mma16816(acc[mt][nt], ah[mt], bh + 2 * g);
                    mma16816(acc[mt][nt], ah[mt], bl + 2 * g);
                    mma16816(acc[mt][nt], al[mt], bh + 2 * g);
                }
            }
        }
    }
}

// ================================================================ init
__global__ void init_kernel(const float* __restrict__ x, float* __restrict__ out) {
    int i = blockIdx.x * blockDim.x + threadIdx.x;
    ((float4*)out)[i] = ((const float4*)x)[i];
    if (blockIdx.x == 0 && threadIdx.x < EE) {
        g_cnt[threadIdx.x] = 0; g_probsum[threadIdx.x] = 0.f; g_loadsum[threadIdx.x] = 0;
    }
}

// ================================================================ transpose + bf16 split
__global__ void transpose_kernel(const float* __restrict__ x) {
    __shared__ float t[32][33];
    int b = blockIdx.z, c0 = blockIdx.y * 32, s0 = blockIdx.x * 32;
    int tx = threadIdx.x, ty = threadIdx.y;
    #pragma unroll
    for (int i = 0; i < 4; i++) {
        int c = c0 + ty + i * 8;
        t[ty + i * 8][tx] = x[(size_t)(b * CC + c) * HHW + s0 + tx];
    }
    __syncthreads();
    #pragma unroll
    for (int i = 0; i < 4; i++) {
        int s = s0 + ty + i * 8;
        float v = t[tx][ty + i * 8];
        __nv_bfloat16 h = __float2bfloat16(v);
        size_t idx = (size_t)(b * HHW + s) * CC + c0 + tx;
        g_xhi[idx] = h;
        g_xlo[idx] = __float2bfloat16(v - __bfloat162float(h));
    }
}

// ================================================================ weight bf16 split
__global__ void convert_w_kernel(const float* __restrict__ sw1, const float* __restrict__ ew1,
                                 const float* __restrict__ sw2, const float* __restrict__ ew2) {
    int i = blockIdx.x * 256 + threadIdx.x;
    float v1 = (i < EE * HHID * CC) ? ew1[i] : sw1[i - EE * HHID * CC];
    __nv_bfloat16 h1 = __float2bfloat16(v1);
    g_w1hi[i] = h1; g_w1lo[i] = __float2bfloat16(v1 - __bfloat162float(h1));
    float v2 = (i < EE * CC * HHID) ? ew2[i] : sw2[i - EE * CC * HHID];
    __nv_bfloat16 h2 = __float2bfloat16(v2);
    g_w2hi[i] = h2; g_w2lo[i] = __float2bfloat16(v2 - __bfloat162float(h2));
}

// ================================================================ router (2 threads/token)
__global__ void router_kernel(const float* __restrict__ x,
                              const float* __restrict__ gw,
                              const float* __restrict__ gb) {
    __shared__ float gws[EE * CC];
    __shared__ int   scnt[EE];
    __shared__ float sprob[EE];
    __shared__ int   sbase[EE];
    int tid = threadIdx.x;
    for (int i = tid; i < EE * CC; i += blockDim.x) gws[i] = gw[i];
    if (tid < EE) { scnt[tid] = 0; sprob[tid] = 0.f; }
    __syncthreads();

    int idx = blockIdx.x * 256 + tid;          // 2*NTOK threads total
    int n = idx >> 1, half = idx & 1;
    int b = n / HHW, s = n - b * HHW;
    const float* xb = x + (size_t)b * CC * HHW + s + (size_t)(half * 64) * HHW;
    const float* gwp = gws + half * 64;

    float acc[EE];
    #pragma unroll
    for (int e = 0; e < EE; e++) acc[e] = half ? 0.f : gb[e];
    #pragma unroll 8
    for (int c = 0; c < 64; c++) {
        float xv = __ldg(&xb[(size_t)c * HHW]);
        #pragma unroll
        for (int e = 0; e < EE; e++) acc[e] += xv * gwp[e * CC + c];
    }
    #pragma unroll
    for (int e = 0; e < EE; e++) acc[e] += __shfl_xor_sync(0xffffffffu, acc[e], 1);

    bool active = (half == 0);
    int id[3]; float pv[3]; float winv = 0.f; int slot[3];
    if (active) {
        float m = acc[0];
        #pragma unroll
        for (int e = 1; e < EE; e++) m = fmaxf(m, acc[e]);
        float sum = 0.f;
        #pragma unroll
        for (int e = 0; e < EE; e++) { acc[e] = expf(acc[e] - m); sum += acc[e]; }
        float inv = 1.f / sum;
        #pragma unroll
        for (int e = 0; e < EE; e++) { acc[e] *= inv; atomicAdd(&sprob[e], acc[e]); }
        float tmp[EE];
        #pragma unroll
        for (int e = 0; e < EE; e++) tmp[e] = acc[e];
        float wsum = 0.f;
        #pragma unroll
        for (int k = 0; k < 3; k++) {
            int bi = 0; float bv = tmp[0];
            #pragma unroll
            for (int e = 1; e < EE; e++) if (tmp[e] > bv) { bv = tmp[e]; bi = e; }
            id[k] = bi; pv[k] = bv; tmp[bi] = -1.f; wsum += bv;
        }
        winv = 1.f / wsum;
        #pragma unroll
        for (int k = 0; k < 3; k++) slot[k] = atomicAdd(&scnt[id[k]], 1);
    }
    __syncthreads();
    if (tid < EE) {
        sbase[tid] = atomicAdd(&g_cnt[tid], scnt[tid]);
        atomicAdd(&g_probsum[tid], sprob[tid]);
        atomicAdd(&g_loadsum[tid], scnt[tid]);
    }
    __syncthreads();
    if (active) {
        #pragma unroll
        for (int k = 0; k < 3; k++) {
            int pos = sbase[id[k]] + slot[k];
            g_tok[id[k] * NTOK + pos] = n;
            g_wt[id[k] * NTOK + pos]  = pv[k] * winv;
        }
    }
}

// ================================================================ aux loss
__global__ void finalize_kernel(float* __restrict__ out, int out_size) {
    if (threadIdx.x == 0) {
        float a = 0.f;
        for (int e = 0; e < EE; e++) a += g_probsum[e] * (float)g_loadsum[e];
        out[out_size - 1] = (float)EE * a / ((float)NTOK * (float)NTOK);
    }
}

// ================================================================ fused MoE (64-token tiles, occ 2)
__global__ __launch_bounds__(256, 2) void moe_mma_kernel(
    const float* __restrict__ sb1, const float* __restrict__ sb2,
    const float* __restrict__ eb1, const float* __restrict__ eb2,
    float* __restrict__ out)
{
    extern __shared__ char sm[];
    uint32_t smb = smem_u32(sm);
    int tid = threadIdx.x, wid = tid >> 5, lid = tid & 31;
    int e = blockIdx.y;

    int count = (e < EE) ? g_cnt[e] : NTOK;
    int t0g = blockIdx.x * TT;
    if (t0g >= count) return;

    const __nv_bfloat16* w1h = g_w1hi + (size_t)e * HHID * CC;
    const __nv_bfloat16* w1l = g_w1lo + (size_t)e * HHID * CC;
    const __nv_bfloat16* w2h = g_w2hi + (size_t)e * CC * HHID;
    const __nv_bfloat16* w2l = g_w2lo + (size_t)e * CC * HHID;
    const float* b1 = (e < EE) ? eb1 + e * HHID : sb1;
    const float* b2 = (e < EE) ? eb2 + e * CC   : sb2;

    int*   tk = (int*)(sm + SM_TK);
    float* tw = (float*)(sm + SM_TW);
    float* bs = (float*)(sm + SM_BS);

    if (tid < TT) {
        int idx = t0g + tid;
        if (e < EE) {
            if (idx < count) { tk[tid] = g_tok[e * NTOK + idx]; tw[tid] = g_wt[e * NTOK + idx]; }
            else             { tk[tid] = 0;                     tw[tid] = 0.f; }
        } else { tk[tid] = idx; tw[tid] = 1.f; }
    }
    __syncthreads();

    // gather pre-split x rows into A tiles via cp.async (64 tokens x 256B each)
    {
        int t = tid >> 2, q = tid & 3;
        int tok = tk[t];
        const char* sh = (const char*)(g_xhi + (size_t)tok * CC) + q * 64;
        const char* sl = (const char*)(g_xlo + (size_t)tok * CC) + q * 64;
        uint32_t dh = smb + SM_A + t * LDA + q * 64;
        #pragma unroll
        for (int i = 0; i < 4; i++) {
            CP16(dh + i * 16,        sh + i * 16);
            CP16(dh + A_LO + i * 16, sl + i * 16);
        }
    }

    int wm = wid & 1, wn = wid >> 1;
    int r_lane = lid >> 2, cq = (lid & 3) * 2;

    float acc2[2][4][4];
    #pragma unroll
    for (int mt = 0; mt < 2; mt++)
        #pragma unroll
        for (int nt = 0; nt < 4; nt++)
            #pragma unroll
            for (int q = 0; q < 4; q++) acc2[mt][nt][q] = 0.f;

    for (int j = 0; j < NCH; j++) {
        // ---- stage W1 chunk [HC rows][128 k] + bias ----
        {
            int row = tid & 63, q = tid >> 6;
            const char* sh = (const char*)(w1h + (size_t)(j * HC + row) * CC) + q * 64;
            const char* sl = (const char*)(w1l + (size_t)(j * HC + row) * CC) + q * 64;
            uint32_t dh = smb + SM_W + row * LDA + q * 64;
            #pragma unroll
            for (int i = 0; i < 4; i++) {
                CP16(dh + i * 16,        sh + i * 16);
                CP16(dh + W_LO + i * 16, sl + i * 16);
            }
            if (tid < HC) bs[tid] = b1[j * HC + tid];
        }
        CP_COMMIT(); CP_WAIT0();
        __syncthreads();

        // ---- GEMM1: [64 tok][64 hid] over K=128 ----
        float acc1[2][2][4];
        #pragma unroll
        for (int mt = 0; mt < 2; mt++)
            #pragma unroll
            for (int g = 0; g < 2; g++)
                #pragma unroll
                for (int q = 0; q < 4; q++) acc1[mt][g][q] = 0.f;
        gemm1_chunk(smb, acc1, lid, wm, wn);
        __syncthreads();   // W1 reads done

        // ---- stage W2 chunk [128 outc][64 k]; epilogue1 -> H hi/lo ----
        {
            int row = tid & 127, hf = tid >> 7;
            const char* src = hf ? (const char*)(w2l + (size_t)row * HHID + j * HC)
                                 : (const char*)(w2h + (size_t)row * HHID + j * HC);
            uint32_t dst = smb + SM_W + row * LDH + hf * W_LO;
            #pragma unroll
            for (int i = 0; i < 8; i++) CP16(dst + i * 16, src + i * 16);
        }
        CP_COMMIT();
        #pragma unroll
        for (int mt = 0; mt < 2; mt++) {
            #pragma unroll
            for (int g = 0; g < 2; g++) {
                int c0 = wn * 16 + g * 8 + cq;
                float bi0 = bs[c0], bi1 = bs[c0 + 1];
                #pragma unroll
                for (int half = 0; half < 2; half++) {
                    int row = wm * 32 + mt * 16 + r_lane + half * 8;
                    float g0 = gelu_exact(acc1[mt][g][half * 2]     + bi0);
                    float g1 = gelu_exact(acc1[mt][g][half * 2 + 1] + bi1);
                    __nv_bfloat16 h0 = __float2bfloat16(g0), h1 = __float2bfloat16(g1);
                    uint32_t hp = ((uint32_t)__bfloat16_as_ushort(h1) << 16) | __bfloat16_as_ushort(h0);
                    __nv_bfloat16 l0 = __float2bfloat16(g0 - __bfloat162float(h0));
                    __nv_bfloat16 l1 = __float2bfloat16(g1 - __bfloat162float(h1));
                    uint32_t lp = ((uint32_t)__bfloat16_as_ushort(l1) << 16) | __bfloat16_as_ushort(l0);
                    *(uint32_t*)(sm + SM_H + row * LDH + c0 * 2) = hp;
                    *(uint32_t*)(sm + SM_H + H_LO + row * LDH + c0 * 2) = lp;
                }
            }
        }
        CP_WAIT0();
        __syncthreads();

        // ---- GEMM2: [64 tok][128 outc] += H . W2^T over this 64-k chunk ----
        gemm2_chunk(smb, acc2, lid, wm, wn);
        __syncthreads();   // W/H free for next chunk
    }

    // ---- final epilogue: weighted atomic scatter ----
    if (tid < CC) bs[tid] = b2[tid];
    __syncthreads();
    #pragma unroll
    for (int mt = 0; mt < 2; mt++) {
        #pragma unroll
        for (int half = 0; half < 2; half++) {
            int t = wm * 32 + mt * 16 + r_lane + half * 8;
            int tok = tk[t];
            float w = tw[t];
            int bb = tok / HHW, s = tok - bb * HHW;
            float* ob = out + (size_t)(bb * CC) * HHW + s;
            #pragma unroll
            for (int nt = 0; nt < 4; nt++) {
                int c0 = wn * 32 + nt * 8 + cq;
                atomicAdd(&ob[(size_t)c0 * HHW],
                          w * (acc2[mt][nt][half * 2]     + bs[c0]));
                atomicAdd(&ob[(size_t)(c0 + 1) * HHW],
                          w * (acc2[mt][nt][half * 2 + 1] + bs[c0 + 1]));
            }
        }
    }
}

// ================================================================
extern "C" void kernel_launch(void* const* d_in, const int* in_sizes, int n_in,
                              void* d_out, int out_size) {
    const float* x   = (const float*)d_in[0];
    const float* sw1 = (const float*)d_in[1];
    const float* sb1 = (const float*)d_in[2];
    const float* sw2 = (const float*)d_in[3];
    const float* sb2 = (const float*)d_in[4];
    const float* gw  = (const float*)d_in[5];
    const float* gb  = (const float*)d_in[6];
    const float* ew1 = (const float*)d_in[7];
    const float* eb1 = (const float*)d_in[8];
    const float* ew2 = (const float*)d_in[9];
    const float* eb2 = (const float*)d_in[10];
    float* out = (float*)d_out;

    cudaFuncSetAttribute(moe_mma_kernel,
                         cudaFuncAttributeMaxDynamicSharedMemorySize, SM_TOTAL);

    init_kernel<<<NOUT / 4 / 256, 256>>>(x, out);
    transpose_kernel<<<dim3(HHW / 32, CC / 32, BB), dim3(32, 8)>>>(x);
    convert_w_kernel<<<W1TOT / 256, 256>>>(sw1, ew1, sw2, ew2);
    router_kernel<<<NTOK * 2 / 256, 256>>>(x, gw, gb);
    moe_mma_kernel<<<dim3(NTOK / TT, EE + 1), 256, SM_TOTAL>>>(sb1, sb2, eb1, eb2, out);
    finalize_kernel<<<1, 32>>>(out, out_size);
}

// round 8
// speedup vs baseline: 1.0473x; 1.0473x over previous
#include <cuda_runtime.h>
#include <cuda_bf16.h>
#include <math.h>
#include <stdint.h>

#define CC    128          // channels
#define HHID  512          // expert hidden dim
#define EE    8            // routed experts
#define BB    8            // batch
#define HHW   9216         // 96*96
#define NTOK  73728        // BB*HHW
#define NOUT  (NTOK*CC)
#define TT    128          // tokens per tile (GEMM M)
#define HC    64           // hidden chunk
#define NCH   (HHID/HC)    // 8 chunks
#define NE1   (EE+1)
#define W1TOT (NE1*HHID*CC)

#define LDA   272          // row stride bytes, K=128 tiles (A, W1)
#define LDH   144          // row stride bytes, K=64 tiles (H, W2)
#define A_SZ  34816        // 128*272 (one A tile)
#define W_SLOT 36864       // one W slot: hi+lo
#define W_LOFF 18432       // lo offset within W slot
#define H_LOFF 18432       // lo offset within H region

// ---- shared memory layout (bytes) ----
#define SM_TK    0
#define SM_TW    512
#define SM_A     1024                    // hi; lo at +A_SZ
#define SM_W     (SM_A + 2*A_SZ)         // 70656; 3 slots of W_SLOT
#define SM_H     (SM_W + 3*W_SLOT)       // 181248; hi, lo at +H_LOFF
#define SM_TOTAL (SM_H + 2*H_LOFF)       // 218112

// ---- device scratch ----
__device__ __nv_bfloat16 g_xhi[(size_t)NTOK*CC];
__device__ __nv_bfloat16 g_xlo[(size_t)NTOK*CC];
__device__ __nv_bfloat16 g_w1hi[W1TOT], g_w1lo[W1TOT];
__device__ __nv_bfloat16 g_w2hi[W1TOT], g_w2lo[W1TOT];
__device__ int   g_tok[EE*NTOK];
__device__ float g_wt[EE*NTOK];
__device__ int   g_cnt[EE];
__device__ float g_probsum[EE];
__device__ int   g_loadsum[EE];

__device__ __forceinline__ float gelu_exact(float v) {
    return 0.5f * v * (1.0f + erff(v * 0.70710678118654752440f));
}
__device__ __forceinline__ uint32_t smem_u32(const void* p) {
    uint32_t a;
    asm("{ .reg .u64 t; cvta.to.shared.u64 t, %1; cvt.u32.u64 %0, t; }" : "=r"(a) : "l"(p));
    return a;
}
#define CP16(s, g)   asm volatile("cp.async.cg.shared.global [%0], [%1], 16;" :: "r"(s), "l"(g) : "memory")
#define CP_COMMIT()  asm volatile("cp.async.commit_group;" ::: "memory")
#define CP_WAIT1()   asm volatile("cp.async.wait_group 1;" ::: "memory")
#define LDM_X4(r0, r1, r2, r3, a) \
    asm volatile("ldmatrix.sync.aligned.m8n8.x4.shared.b16 {%0,%1,%2,%3}, [%4];" \
        : "=r"(r0), "=r"(r1), "=r"(r2), "=r"(r3) : "r"(a))

__device__ __forceinline__ void mma16816(float* d, const uint32_t* a, const uint32_t* b) {
    asm volatile("mma.sync.aligned.m16n8k16.row.col.f32.bf16.bf16.f32 "
        "{%0,%1,%2,%3}, {%4,%5,%6,%7}, {%8,%9}, {%0,%1,%2,%3};"
        : "+f"(d[0]), "+f"(d[1]), "+f"(d[2]), "+f"(d[3])
        : "r"(a[0]), "r"(a[1]), "r"(a[2]), "r"(a[3]), "r"(b[0]), "r"(b[1]));
}

// GEMM1: [128 tok] x [64 hid] over K=128, 3-pass. Warps 4(m) x 2(n); warp tile 32x32.
__device__ __forceinline__ void gemm1(uint32_t smb, uint32_t wslot, float acc[2][4][4],
                                      int lid, int wm, int wn) {
    int a_r  = (lid & 7) + ((lid >> 3) & 1) * 8;
    int a_ko = ((lid >> 4) & 1) * 16;
    int b_n  = (lid & 7) + ((lid >> 4) & 1) * 8;
    int b_ko = ((lid >> 3) & 1) * 16;
    uint32_t aBase = smb + SM_A + (uint32_t)(wm * 32 + a_r) * LDA + a_ko;
    uint32_t bBase = wslot + (uint32_t)(wn * 32 + b_n) * LDA + b_ko;
    #pragma unroll 2
    for (int k0 = 0; k0 < 8; k0++) {
        uint32_t kb = k0 * 32;
        uint32_t ah[2][4], al[2][4];
        #pragma unroll
        for (int mt = 0; mt < 2; mt++) {
            uint32_t ad = aBase + (uint32_t)(mt * 16) * LDA + kb;
            LDM_X4(ah[mt][0], ah[mt][1], ah[mt][2], ah[mt][3], ad);
            LDM_X4(al[mt][0], al[mt][1], al[mt][2], al[mt][3], ad + A_SZ);
        }
        #pragma unroll
        for (int ntp = 0; ntp < 2; ntp++) {
            uint32_t bd = bBase + (uint32_t)(ntp * 16) * LDA + kb;
            uint32_t bh[4], bl[4];
            LDM_X4(bh[0], bh[1], bh[2], bh[3], bd);
            LDM_X4(bl[0], bl[1], bl[2], bl[3], bd + W_LOFF);
            #pragma unroll
            for (int g = 0; g < 2; g++) {
                int nt = ntp * 2 + g;
                #pragma unroll
                for (int mt = 0; mt < 2; mt++) {
                    mma16816(acc[mt][nt], ah[mt], bh + 2 * g);
                    mma16816(acc[mt][nt], ah[mt], bl + 2 * g);
                    mma16816(acc[mt][nt], al[mt], bh + 2 * g);
                }
            }
        }
    }
}

// GEMM2: [128 tok] x [128 outc] over K=64, 3-pass. Warps 4(m) x 2(n); warp tile 32x64.
__device__ __forceinline__ void gemm2(uint32_t smb, uint32_t wslot, float acc[2][8][4],
                                      int lid, int wm, int wn) {
    int a_r  = (lid & 7) + ((lid >> 3) & 1) * 8;
    int a_ko = ((lid >> 4) & 1) * 16;
    int b_n  = (lid & 7) + ((lid >> 4) & 1) * 8;
    int b_ko = ((lid >> 3) & 1) * 16;
    uint32_t aBase = smb + SM_H + (uint32_t)(wm * 32 + a_r) * LDH + a_ko;
    uint32_t bBase = wslot + (uint32_t)(wn * 64 + b_n) * LDH + b_ko;
    #pragma unroll
    for (int k0 = 0; k0 < 4; k0++) {
        uint32_t kb = k0 * 32;
        uint32_t ah[2][4], al[2][4];
        #pragma unroll
        for (int mt = 0; mt < 2; mt++) {
            uint32_t ad = aBase + (uint32_t)(mt * 16) * LDH + kb;
            LDM_X4(ah[mt][0], ah[mt][1], ah[mt][2], ah[mt][3], ad);
            LDM_X4(al[mt][0], al[mt][1], al[mt][2], al[mt][3], ad + H_LOFF);
        }
        #pragma unroll
        for (int ntp = 0; ntp < 4; ntp++) {
            uint32_t bd = bBase + (uint32_t)(ntp * 16) * LDH + kb;
            uint32_t bh[4], bl[4];
            LDM_X4(bh[0], bh[1], bh[2], bh[3], bd);
            LDM_X4(bl[0], bl[1], bl[2], bl[3], bd + W_LOFF);
            #pragma unroll
            for (int g = 0; g < 2; g++) {
                int nt = ntp * 2 + g;
                #pragma unroll
                for (int mt = 0; mt < 2; mt++) {
                    mma16816(acc[mt][nt], ah[mt], bh + 2 * g);
                    mma16816(acc[mt][nt], ah[mt], bl + 2 * g);
                    mma16816(acc[mt][nt], al[mt], bh + 2 * g);
                }
            }
        }
    }
}

// ================================================================ init
__global__ void init_kernel(const float* __restrict__ x, float* __restrict__ out) {
    int i = blockIdx.x * blockDim.x + threadIdx.x;
    ((float4*)out)[i] = ((const float4*)x)[i];
    if (blockIdx.x == 0 && threadIdx.x < EE) {
        g_cnt[threadIdx.x] = 0; g_probsum[threadIdx.x] = 0.f; g_loadsum[threadIdx.x] = 0;
    }
}

// ================================================================ transpose + bf16 split
__global__ void transpose_kernel(const float* __restrict__ x) {
    __shared__ float t[32][33];
    int b = blockIdx.z, c0 = blockIdx.y * 32, s0 = blockIdx.x * 32;
    int tx = threadIdx.x, ty = threadIdx.y;
    #pragma unroll
    for (int i = 0; i < 4; i++) {
        int c = c0 + ty + i * 8;
        t[ty + i * 8][tx] = x[(size_t)(b * CC + c) * HHW + s0 + tx];
    }
    __syncthreads();
    #pragma unroll
    for (int i = 0; i < 4; i++) {
        int s = s0 + ty + i * 8;
        float v = t[tx][ty + i * 8];
        __nv_bfloat16 h = __float2bfloat16(v);
        size_t idx = (size_t)(b * HHW + s) * CC + c0 + tx;
        g_xhi[idx] = h;
        g_xlo[idx] = __float2bfloat16(v - __bfloat162float(h));
    }
}

// ================================================================ weight bf16 split
__global__ void convert_w_kernel(const float* __restrict__ sw1, const float* __restrict__ ew1,
                                 const float* __restrict__ sw2, const float* __restrict__ ew2) {
    int i = blockIdx.x * 256 + threadIdx.x;
    float v1 = (i < EE * HHID * CC) ? ew1[i] : sw1[i - EE * HHID * CC];
    __nv_bfloat16 h1 = __float2bfloat16(v1);
    g_w1hi[i] = h1; g_w1lo[i] = __float2bfloat16(v1 - __bfloat162float(h1));
    float v2 = (i < EE * CC * HHID) ? ew2[i] : sw2[i - EE * CC * HHID];
    __nv_bfloat16 h2 = __float2bfloat16(v2);
    g_w2hi[i] = h2; g_w2lo[i] = __float2bfloat16(v2 - __bfloat162float(h2));
}

// ================================================================ router (2 threads/token)
__global__ void router_kernel(const float* __restrict__ x,
                              const float* __restrict__ gw,
                              const float* __restrict__ gb) {
    __shared__ float gws[EE * CC];
    __shared__ int   scnt[EE];
    __shared__ float sprob[EE];
    __shared__ int   sbase[EE];
    int tid = threadIdx.x;
    for (int i = tid; i < EE * CC; i += blockDim.x) gws[i] = gw[i];
    if (tid < EE) { scnt[tid] = 0; sprob[tid] = 0.f; }
    __syncthreads();

    int idx = blockIdx.x * 256 + tid;
    int n = idx >> 1, half = idx & 1;
    int b = n / HHW, s = n - b * HHW;
    const float* xb = x + (size_t)b * CC * HHW + s + (size_t)(half * 64) * HHW;
    const float* gwp = gws + half * 64;

    float acc[EE];
    #pragma unroll
    for (int e = 0; e < EE; e++) acc[e] = half ? 0.f : gb[e];
    #pragma unroll 8
    for (int c = 0; c < 64; c++) {
        float xv = __ldg(&xb[(size_t)c * HHW]);
        #pragma unroll
        for (int e = 0; e < EE; e++) acc[e] += xv * gwp[e * CC + c];
    }
    #pragma unroll
    for (int e = 0; e < EE; e++) acc[e] += __shfl_xor_sync(0xffffffffu, acc[e], 1);

    bool active = (half == 0);
    int id[3]; float pv[3]; float winv = 0.f; int slot[3];
    if (active) {
        float m = acc[0];
        #pragma unroll
        for (int e = 1; e < EE; e++) m = fmaxf(m, acc[e]);
        float sum = 0.f;
        #pragma unroll
        for (int e = 0; e < EE; e++) { acc[e] = expf(acc[e] - m); sum += acc[e]; }
        float inv = 1.f / sum;
        #pragma unroll
        for (int e = 0; e < EE; e++) { acc[e] *= inv; atomicAdd(&sprob[e], acc[e]); }
        float tmp[EE];
        #pragma unroll
        for (int e = 0; e < EE; e++) tmp[e] = acc[e];
        float wsum = 0.f;
        #pragma unroll
        for (int k = 0; k < 3; k++) {
            int bi = 0; float bv = tmp[0];
            #pragma unroll
            for (int e = 1; e < EE; e++) if (tmp[e] > bv) { bv = tmp[e]; bi = e; }
            id[k] = bi; pv[k] = bv; tmp[bi] = -1.f; wsum += bv;
        }
        winv = 1.f / wsum;
        #pragma unroll
        for (int k = 0; k < 3; k++) slot[k] = atomicAdd(&scnt[id[k]], 1);
    }
    __syncthreads();
    if (tid < EE) {
        sbase[tid] = atomicAdd(&g_cnt[tid], scnt[tid]);
        atomicAdd(&g_probsum[tid], sprob[tid]);
        atomicAdd(&g_loadsum[tid], scnt[tid]);
    }
    __syncthreads();
    if (active) {
        #pragma unroll
        for (int k = 0; k < 3; k++) {
            int pos = sbase[id[k]] + slot[k];
            g_tok[id[k] * NTOK + pos] = n;
            g_wt[id[k] * NTOK + pos]  = pv[k] * winv;
        }
    }
}

// ================================================================ aux loss
__global__ void finalize_kernel(float* __restrict__ out, int out_size) {
    if (threadIdx.x == 0) {
        float a = 0.f;
        for (int e = 0; e < EE; e++) a += g_probsum[e] * (float)g_loadsum[e];
        out[out_size - 1] = (float)EE * a / ((float)NTOK * (float)NTOK);
    }
}

// ================================================================ fused MoE (TT=128, pipelined W staging)
__global__ __launch_bounds__(256, 1) void moe_mma_kernel(
    const float* __restrict__ sb1, const float* __restrict__ sb2,
    const float* __restrict__ eb1, const float* __restrict__ eb2,
    float* __restrict__ out)
{
    extern __shared__ char sm[];
    uint32_t smb = smem_u32(sm);
    int tid = threadIdx.x, wid = tid >> 5, lid = tid & 31;
    int e = blockIdx.y;

    int count = (e < EE) ? g_cnt[e] : NTOK;
    int t0g = blockIdx.x * TT;
    if (t0g >= count) return;

    const __nv_bfloat16* w1h = g_w1hi + (size_t)e * HHID * CC;
    const __nv_bfloat16* w1l = g_w1lo + (size_t)e * HHID * CC;
    const __nv_bfloat16* w2h = g_w2hi + (size_t)e * CC * HHID;
    const __nv_bfloat16* w2l = g_w2lo + (size_t)e * CC * HHID;
    const float* b1 = (e < EE) ? eb1 + e * HHID : sb1;
    const float* b2 = (e < EE) ? eb2 + e * CC   : sb2;

    int*   tk = (int*)(sm + SM_TK);
    float* tw = (float*)(sm + SM_TW);

    if (tid < TT) {
        int idx = t0g + tid;
        if (e < EE) {
            if (idx < count) { tk[tid] = g_tok[e * NTOK + idx]; tw[tid] = g_wt[e * NTOK + idx]; }
            else             { tk[tid] = 0;                     tw[tid] = 0.f; }
        } else { tk[tid] = idx; tw[tid] = 1.f; }
    }
    __syncthreads();

    // staging lambdas
    int w1row = tid & 63, w1part = (tid >> 6) & 3;           // 64 rows x 4 x 64B
    int w2row = tid & 127, w2hf = tid >> 7;                  // 128 rows x (hi|lo) 128B

    // A gather: 128 tokens x (hi+lo) 256B each
    {
        int t = tid >> 1, q = tid & 1;
        int tok = tk[t];
        const char* sh = (const char*)(g_xhi + (size_t)tok * CC) + q * 128;
        const char* sl = (const char*)(g_xlo + (size_t)tok * CC) + q * 128;
        uint32_t dh = smb + SM_A + t * LDA + q * 128;
        #pragma unroll
        for (int i = 0; i < 8; i++) {
            CP16(dh + i * 16,        sh + i * 16);
            CP16(dh + A_SZ + i * 16, sl + i * 16);
        }
    }
    // stage W1[0] into slot 0, commit with A (C0)
    {
        const char* sh = (const char*)(w1h + (size_t)w1row * CC) + w1part * 64;
        const char* sl = (const char*)(w1l + (size_t)w1row * CC) + w1part * 64;
        uint32_t d = smb + SM_W + w1row * LDA + w1part * 64;
        #pragma unroll
        for (int i = 0; i < 4; i++) {
            CP16(d + i * 16,          sh + i * 16);
            CP16(d + W_LOFF + i * 16, sl + i * 16);
        }
    }
    CP_COMMIT();   // C0 = A + W1[0]
    // stage W2[0] into slot 1, commit (C1)
    {
        const char* src = w2hf ? (const char*)(w2l + (size_t)w2row * HHID)
                               : (const char*)(w2h + (size_t)w2row * HHID);
        uint32_t d = smb + SM_W + W_SLOT + w2row * LDH + w2hf * W_LOFF;
        #pragma unroll
        for (int i = 0; i < 8; i++) CP16(d + i * 16, src + i * 16);
    }
    CP_COMMIT();   // C1 = W2[0]

    int wm = wid & 3, wn = wid >> 2;
    int r_lane = lid >> 2, cq = (lid & 3) * 2;

    float acc2[2][8][4];
    #pragma unroll
    for (int mt = 0; mt < 2; mt++)
        #pragma unroll
        for (int nt = 0; nt < 8; nt++)
            #pragma unroll
            for (int q = 0; q < 4; q++) acc2[mt][nt][q] = 0.f;

    for (int j = 0; j < NCH; j++) {
        uint32_t slot1 = smb + SM_W + (uint32_t)(((2 * j) % 3) * W_SLOT);
        uint32_t slot2 = smb + SM_W + (uint32_t)(((2 * j + 1) % 3) * W_SLOT);

        CP_WAIT1();            // W1[j] (and A) landed
        __syncthreads();

        // prefetch W1[j+1] into slot (2j+2)%3
        if (j + 1 < NCH) {
            uint32_t d = smb + SM_W + (uint32_t)(((2 * j + 2) % 3) * W_SLOT)
                       + w1row * LDA + w1part * 64;
            const char* sh = (const char*)(w1h + (size_t)((j + 1) * HC + w1row) * CC) + w1part * 64;
            const char* sl = (const char*)(w1l + (size_t)((j + 1) * HC + w1row) * CC) + w1part * 64;
            #pragma unroll
            for (int i = 0; i < 4; i++) {
                CP16(d + i * 16,          sh + i * 16);
                CP16(d + W_LOFF + i * 16, sl + i * 16);
            }
        }
        CP_COMMIT();

        // ---- GEMM1: [128 tok][64 hid] ----
        float acc1[2][4][4];
        #pragma unroll
        for (int mt = 0; mt < 2; mt++)
            #pragma unroll
            for (int nt = 0; nt < 4; nt++)
                #pragma unroll
                for (int q = 0; q < 4; q++) acc1[mt][nt][q] = 0.f;
        gemm1(smb, slot1, acc1, lid, wm, wn);

        CP_WAIT1();            // W2[j] landed
        __syncthreads();       // also closes all GEMM1 reads of slot1

        // prefetch W2[j+1] into slot (2j+3)%3 (= slot1's slot, reads closed above)
        if (j + 1 < NCH) {
            uint32_t d = smb + SM_W + (uint32_t)(((2 * j + 3) % 3) * W_SLOT)
                       + w2row * LDH + w2hf * W_LOFF;
            const char* src = w2hf ? (const char*)(w2l + (size_t)w2row * HHID + (j + 1) * HC)
                                   : (const char*)(w2h + (size_t)w2row * HHID + (j + 1) * HC);
            #pragma unroll
            for (int i = 0; i < 8; i++) CP16(d + i * 16, src + i * 16);
        }
        CP_COMMIT();

        // ---- epilogue1: bias+gelu -> H (hi/lo) ----
        #pragma unroll
        for (int mt = 0; mt < 2; mt++) {
            #pragma unroll
            for (int nt = 0; nt < 4; nt++) {
                int c0 = wn * 32 + nt * 8 + cq;
                float bi0 = __ldg(&b1[j * HC + c0]);
                float bi1 = __ldg(&b1[j * HC + c0 + 1]);
                #pragma unroll
                for (int half = 0; half < 2; half++) {
                    int row = wm * 32 + mt * 16 + r_lane + half * 8;
                    float g0 = gelu_exact(acc1[mt][nt][half * 2]     + bi0);
                    float g1 = gelu_exact(acc1[mt][nt][half * 2 + 1] + bi1);
                    __nv_bfloat16 h0 = __float2bfloat16(g0), h1 = __float2bfloat16(g1);
                    uint32_t hp = ((uint32_t)__bfloat16_as_ushort(h1) << 16) | __bfloat16_as_ushort(h0);
                    __nv_bfloat16 l0 = __float2bfloat16(g0 - __bfloat162float(h0));
                    __nv_bfloat16 l1 = __float2bfloat16(g1 - __bfloat162float(h1));
                    uint32_t lp = ((uint32_t)__bfloat16_as_ushort(l1) << 16) | __bfloat16_as_ushort(l0);
                    *(uint32_t*)(sm + SM_H + row * LDH + c0 * 2) = hp;
                    *(uint32_t*)(sm + SM_H + H_LOFF + row * LDH + c0 * 2) = lp;
                }
            }
        }
        __syncthreads();       // H visible

        // ---- GEMM2: [128 tok][128 outc] += H . W2^T ----
        gemm2(smb, slot2, acc2, lid, wm, wn);
        // top-of-next-iter sync closes GEMM2 reads of slot2 before its slot is rewritten
    }

    // ---- final epilogue: weighted atomic scatter ----
    #pragma unroll
    for (int mt = 0; mt < 2; mt++) {
        #pragma unroll
        for (int half = 0; half < 2; half++) {
            int t = wm * 32 + mt * 16 + r_lane + half * 8;
            int tok = tk[t];
            float w = tw[t];
            int bb = tok / HHW, s = tok - bb * HHW;
            float* ob = out + (size_t)(bb * CC) * HHW + s;
            #pragma unroll
            for (int nt = 0; nt < 8; nt++) {
                int c0 = wn * 64 + nt * 8 + cq;
                atomicAdd(&ob[(size_t)c0 * HHW],
                          w * (acc2[mt][nt][half * 2]     + __ldg(&b2[c0])));
                atomicAdd(&ob[(size_t)(c0 + 1) * HHW],
                          w * (acc2[mt][nt][half * 2 + 1] + __ldg(&b2[c0 + 1])));
            }
        }
    }
}

// ================================================================
extern "C" void kernel_launch(void* const* d_in, const int* in_sizes, int n_in,
                              void* d_out, int out_size) {
    const float* x   = (const float*)d_in[0];
    const float* sw1 = (const float*)d_in[1];
    const float* sb1 = (const float*)d_in[2];
    const float* sw2 = (const float*)d_in[3];
    const float* sb2 = (const float*)d_in[4];
    const float* gw  = (const float*)d_in[5];
    const float* gb  = (const float*)d_in[6];
    const float* ew1 = (const float*)d_in[7];
    const float* eb1 = (const float*)d_in[8];
    const float* ew2 = (const float*)d_in[9];
    const float* eb2 = (const float*)d_in[10];
    float* out = (float*)d_out;

    cudaFuncSetAttribute(moe_mma_kernel,
                         cudaFuncAttributeMaxDynamicSharedMemorySize, SM_TOTAL);

    init_kernel<<<NOUT / 4 / 256, 256>>>(x, out);
    transpose_kernel<<<dim3(HHW / 32, CC / 32, BB), dim3(32, 8)>>>(x);
    convert_w_kernel<<<W1TOT / 256, 256>>>(sw1, ew1, sw2, ew2);
    router_kernel<<<NTOK * 2 / 256, 256>>>(x, gw, gb);
    moe_mma_kernel<<<dim3(NTOK / TT, EE + 1), 256, SM_TOTAL>>>(sb1, sb2, eb1, eb2, out);
    finalize_kernel<<<1, 32>>>(out, out_size);
}

// round 9
// speedup vs baseline: 1.4762x; 1.4096x over previous
#include <cuda_runtime.h>
#include <cuda_fp16.h>
#include <math.h>
#include <stdint.h>

#define CC    128          // channels
#define HHID  512          // expert hidden dim
#define EE    8            // routed experts
#define BB    8            // batch
#define HHW   9216         // 96*96
#define NTOK  73728        // BB*HHW
#define NOUT  (NTOK*CC)
#define TMT   128          // tokens per tile (GEMM M)
#define NE1   (EE+1)
#define W1TOT (NE1*HHID*CC)

#define LDB   272          // smem row stride in bytes (136 fp16: 128 + 8 pad)
#define TILEB (128*LDB)    // 34816 B per tile

// ---- shared memory layout (bytes); A/H lo at +TILEB; W has no lo ----
#define SM_TK    0
#define SM_TW    512
#define SM_BIAS  1024
#define SM_AHI   2048
#define SM_ALO   (SM_AHI+TILEB)
#define SM_W     (SM_ALO+TILEB)
#define SM_HHI   (SM_W+TILEB)
#define SM_HLO   (SM_HHI+TILEB)
#define SM_TOTAL (SM_HLO+TILEB)   // 176128 B

// ---- device scratch ----
__device__ __half g_xhi[(size_t)NTOK*CC];
__device__ __half g_xlo[(size_t)NTOK*CC];
__device__ __half g_w1h[W1TOT];
__device__ __half g_w2h[W1TOT];
__device__ int   g_tok[EE*NTOK];
__device__ float g_wt[EE*NTOK];
__device__ int   g_cnt[EE];
__device__ float g_probsum[EE];
__device__ int   g_loadsum[EE];

__device__ __forceinline__ float gelu_exact(float v) {
    return 0.5f * v * (1.0f + erff(v * 0.70710678118654752440f));
}
__device__ __forceinline__ uint32_t smem_u32(const void* p) {
    uint32_t a;
    asm("{ .reg .u64 t; cvta.to.shared.u64 t, %1; cvt.u32.u64 %0, t; }" : "=r"(a) : "l"(p));
    return a;
}
#define CP16(s, g)   asm volatile("cp.async.cg.shared.global [%0], [%1], 16;" :: "r"(s), "l"(g) : "memory")
#define CP_COMMIT()  asm volatile("cp.async.commit_group;" ::: "memory")
#define CP_WAIT0()   asm volatile("cp.async.wait_group 0;" ::: "memory")
#define LDM_X4(r0, r1, r2, r3, a) \
    asm volatile("ldmatrix.sync.aligned.m8n8.x4.shared.b16 {%0,%1,%2,%3}, [%4];" \
        : "=r"(r0), "=r"(r1), "=r"(r2), "=r"(r3) : "r"(a))

__device__ __forceinline__ void mma16816(float* d, const uint32_t* a, const uint32_t* b) {
    asm volatile("mma.sync.aligned.m16n8k16.row.col.f32.f16.f16.f32 "
        "{%0,%1,%2,%3}, {%4,%5,%6,%7}, {%8,%9}, {%0,%1,%2,%3};"
        : "+f"(d[0]), "+f"(d[1]), "+f"(d[2]), "+f"(d[3])
        : "r"(a[0]), "r"(a[1]), "r"(a[2]), "r"(a[3]), "r"(b[0]), "r"(b[1]));
}

// one 128x128x128 GEMM chunk, 2-pass fp16 (A split hi/lo at aHi/+TILEB, W single at wHi).
// acc[mt][nt][4] accumulates [32 tok][64 cols] per warp. Warps 4(m) x 2(n).
__device__ __forceinline__ void gemm_chunk(uint32_t aHi, uint32_t wHi,
                                           float acc[2][8][4], int lid, int wm, int wn) {
    int a_r  = (lid & 7) + ((lid >> 3) & 1) * 8;
    int a_ko = ((lid >> 4) & 1) * 16;
    int b_n  = (lid & 7) + ((lid >> 4) & 1) * 8;
    int b_ko = ((lid >> 3) & 1) * 16;
    uint32_t aBase = aHi + (uint32_t)(wm * 32 + a_r) * LDB + a_ko;
    uint32_t bBase = wHi + (uint32_t)(wn * 64 + b_n) * LDB + b_ko;

    #pragma unroll 2
    for (int k0 = 0; k0 < 8; k0++) {
        uint32_t kb = k0 * 32;
        uint32_t ah[2][4], al[2][4];
        #pragma unroll
        for (int mt = 0; mt < 2; mt++) {
            uint32_t ad = aBase + (uint32_t)(mt * 16) * LDB + kb;
            LDM_X4(ah[mt][0], ah[mt][1], ah[mt][2], ah[mt][3], ad);
            LDM_X4(al[mt][0], al[mt][1], al[mt][2], al[mt][3], ad + TILEB);
        }
        #pragma unroll
        for (int ntp = 0; ntp < 4; ntp++) {
            uint32_t bd = bBase + (uint32_t)(ntp * 16) * LDB + kb;
            uint32_t bh[4];
            LDM_X4(bh[0], bh[1], bh[2], bh[3], bd);
            #pragma unroll
            for (int g = 0; g < 2; g++) {
                int nt = ntp * 2 + g;
                #pragma unroll
                for (int mt = 0; mt < 2; mt++) {
                    mma16816(acc[mt][nt], ah[mt], bh + 2 * g);
                    mma16816(acc[mt][nt], al[mt], bh + 2 * g);
                }
            }
        }
    }
}

// ================================================================ init
__global__ void init_kernel(const float* __restrict__ x, float* __restrict__ out) {
    int i = blockIdx.x * blockDim.x + threadIdx.x;
    ((float4*)out)[i] = ((const float4*)x)[i];
    if (blockIdx.x == 0 && threadIdx.x < EE) {
        g_cnt[threadIdx.x] = 0; g_probsum[threadIdx.x] = 0.f; g_loadsum[threadIdx.x] = 0;
    }
}

// ================================================================ transpose + fp16 split
__global__ void transpose_kernel(const float* __restrict__ x) {
    __shared__ float t[32][33];
    int b = blockIdx.z, c0 = blockIdx.y * 32, s0 = blockIdx.x * 32;
    int tx = threadIdx.x, ty = threadIdx.y;
    #pragma unroll
    for (int i = 0; i < 4; i++) {
        int c = c0 + ty + i * 8;
        t[ty + i * 8][tx] = x[(size_t)(b * CC + c) * HHW + s0 + tx];
    }
    __syncthreads();
    #pragma unroll
    for (int i = 0; i < 4; i++) {
        int s = s0 + ty + i * 8;
        float v = t[tx][ty + i * 8];
        __half h = __float2half(v);
        size_t idx = (size_t)(b * HHW + s) * CC + c0 + tx;
        g_xhi[idx] = h;
        g_xlo[idx] = __float2half(v - __half2float(h));
    }
}

// ================================================================ weight fp16 convert (single precision level)
__global__ void convert_w_kernel(const float* __restrict__ sw1, const float* __restrict__ ew1,
                                 const float* __restrict__ sw2, const float* __restrict__ ew2) {
    int i = blockIdx.x * 256 + threadIdx.x;
    float v1 = (i < EE * HHID * CC) ? ew1[i] : sw1[i - EE * HHID * CC];
    g_w1h[i] = __float2half(v1);
    float v2 = (i < EE * CC * HHID) ? ew2[i] : sw2[i - EE * CC * HHID];
    g_w2h[i] = __float2half(v2);
}

// ================================================================ router (2 threads/token)
__global__ void router_kernel(const float* __restrict__ x,
                              const float* __restrict__ gw,
                              const float* __restrict__ gb) {
    __shared__ float gws[EE * CC];
    __shared__ int   scnt[EE];
    __shared__ float sprob[EE];
    __shared__ int   sbase[EE];
    int tid = threadIdx.x;
    for (int i = tid; i < EE * CC; i += blockDim.x) gws[i] = gw[i];
    if (tid < EE) { scnt[tid] = 0; sprob[tid] = 0.f; }
    __syncthreads();

    int idx = blockIdx.x * 256 + tid;
    int n = idx >> 1, half = idx & 1;
    int b = n / HHW, s = n - b * HHW;
    const float* xb = x + (size_t)b * CC * HHW + s + (size_t)(half * 64) * HHW;
    const float* gwp = gws + half * 64;

    float acc[EE];
    #pragma unroll
    for (int e = 0; e < EE; e++) acc[e] = half ? 0.f : gb[e];
    #pragma unroll 8
    for (int c = 0; c < 64; c++) {
        float xv = __ldg(&xb[(size_t)c * HHW]);
        #pragma unroll
        for (int e = 0; e < EE; e++) acc[e] += xv * gwp[e * CC + c];
    }
    #pragma unroll
    for (int e = 0; e < EE; e++) acc[e] += __shfl_xor_sync(0xffffffffu, acc[e], 1);

    bool active = (half == 0);
    int id[3]; float pv[3]; float winv = 0.f; int slot[3];
    if (active) {
        float m = acc[0];
        #pragma unroll
        for (int e = 1; e < EE; e++) m = fmaxf(m, acc[e]);
        float sum = 0.f;
        #pragma unroll
        for (int e = 0; e < EE; e++) { acc[e] = expf(acc[e] - m); sum += acc[e]; }
        float inv = 1.f / sum;
        #pragma unroll
        for (int e = 0; e < EE; e++) { acc[e] *= inv; atomicAdd(&sprob[e], acc[e]); }
        float tmp[EE];
        #pragma unroll
        for (int e = 0; e < EE; e++) tmp[e] = acc[e];
        float wsum = 0.f;
        #pragma unroll
        for (int k = 0; k < 3; k++) {
            int bi = 0; float bv = tmp[0];
            #pragma unroll
            for (int e = 1; e < EE; e++) if (tmp[e] > bv) { bv = tmp[e]; bi = e; }
            id[k] = bi; pv[k] = bv; tmp[bi] = -1.f; wsum += bv;
        }
        winv = 1.f / wsum;
        #pragma unroll
        for (int k = 0; k < 3; k++) slot[k] = atomicAdd(&scnt[id[k]], 1);
    }
    __syncthreads();
    if (tid < EE) {
        sbase[tid] = atomicAdd(&g_cnt[tid], scnt[tid]);
        atomicAdd(&g_probsum[tid], sprob[tid]);
        atomicAdd(&g_loadsum[tid], scnt[tid]);
    }
    __syncthreads();
    if (active) {
        #pragma unroll
        for (int k = 0; k < 3; k++) {
            int pos = sbase[id[k]] + slot[k];
            g_tok[id[k] * NTOK + pos] = n;
            g_wt[id[k] * NTOK + pos]  = pv[k] * winv;
        }
    }
}

// ================================================================ aux loss
__global__ void finalize_kernel(float* __restrict__ out, int out_size) {
    if (threadIdx.x == 0) {
        float a = 0.f;
        for (int e = 0; e < EE; e++) a += g_probsum[e] * (float)g_loadsum[e];
        out[out_size - 1] = (float)EE * a / ((float)NTOK * (float)NTOK);
    }
}

// ================================================================ fused MoE (HMMA fp16 2-pass)
__global__ __launch_bounds__(256, 1) void moe_mma_kernel(
    const float* __restrict__ sb1, const float* __restrict__ sb2,
    const float* __restrict__ eb1, const float* __restrict__ eb2,
    float* __restrict__ out)
{
    extern __shared__ char sm[];
    uint32_t smb = smem_u32(sm);
    int tid = threadIdx.x, wid = tid >> 5, lid = tid & 31;
    int e = blockIdx.y;

    int count = (e < EE) ? g_cnt[e] : NTOK;
    int t0g = blockIdx.x * TMT;
    if (t0g >= count) return;

    const __half* w1h = g_w1h + (size_t)e * HHID * CC;
    const __half* w2h = g_w2h + (size_t)e * CC * HHID;
    const float* b1 = (e < EE) ? eb1 + e * HHID : sb1;
    const float* b2 = (e < EE) ? eb2 + e * CC   : sb2;

    int*   tk = (int*)(sm + SM_TK);
    float* tw = (float*)(sm + SM_TW);
    float* bs = (float*)(sm + SM_BIAS);

    if (tid < TMT) {
        int idx = t0g + tid;
        if (e < EE) {
            if (idx < count) { tk[tid] = g_tok[e * NTOK + idx]; tw[tid] = g_wt[e * NTOK + idx]; }
            else             { tk[tid] = 0;                     tw[tid] = 0.f; }
        } else { tk[tid] = idx; tw[tid] = 1.f; }
    }
    __syncthreads();

    // gather pre-split x rows into A tiles via cp.async (hi + lo, 256B each)
    {
        int t = tid >> 1, hf = tid & 1;
        int tok = tk[t];
        const char* sh = (const char*)(g_xhi + (size_t)tok * CC) + hf * 128;
        const char* sl = (const char*)(g_xlo + (size_t)tok * CC) + hf * 128;
        uint32_t dh = smb + SM_AHI + t * LDB + hf * 128;
        #pragma unroll
        for (int i = 0; i < 8; i++) {
            CP16(dh + i * 16,         sh + i * 16);
            CP16(dh + TILEB + i * 16, sl + i * 16);
        }
    }

    int wm = wid & 3, wn = wid >> 2;
    int r_lane = lid >> 2;
    int stg_n = tid & 127, stg_h = tid >> 7;   // staging: row, 128B half

    float acc2[2][8][4];
    #pragma unroll
    for (int mt = 0; mt < 2; mt++)
        #pragma unroll
        for (int nt = 0; nt < 8; nt++)
            #pragma unroll
            for (int q = 0; q < 4; q++) acc2[mt][nt][q] = 0.f;

    for (int j = 0; j < 4; j++) {
        // ---- stage w1 chunk rows [hid_out][k=C] (hi only) + bias ----
        {
            const char* sh = (const char*)(w1h + (size_t)(j * 128 + stg_n) * CC) + stg_h * 128;
            uint32_t dh = smb + SM_W + stg_n * LDB + stg_h * 128;
            #pragma unroll
            for (int i = 0; i < 8; i++) CP16(dh + i * 16, sh + i * 16);
            if (tid < 128) bs[tid] = b1[j * 128 + tid];
        }
        CP_COMMIT(); CP_WAIT0();
        __syncthreads();

        // ---- GEMM1: [128 tok][128 hid] over K=128, 2-pass ----
        float acc1[2][8][4];
        #pragma unroll
        for (int mt = 0; mt < 2; mt++)
            #pragma unroll
            for (int nt = 0; nt < 8; nt++)
                #pragma unroll
                for (int q = 0; q < 4; q++) acc1[mt][nt][q] = 0.f;
        gemm_chunk(smb + SM_AHI, smb + SM_W, acc1, lid, wm, wn);
        __syncthreads();   // GEMM1 reads of W done

        // ---- stage w2 chunk [128 outc][k=hid chunk] (hi only); epilogue1 -> H hi/lo ----
        {
            const char* sh = (const char*)(w2h + (size_t)stg_n * HHID + j * 128) + stg_h * 128;
            uint32_t dh = smb + SM_W + stg_n * LDB + stg_h * 128;
            #pragma unroll
            for (int i = 0; i < 8; i++) CP16(dh + i * 16, sh + i * 16);
        }
        CP_COMMIT();
        #pragma unroll
        for (int mt = 0; mt < 2; mt++) {
            #pragma unroll
            for (int nt = 0; nt < 8; nt++) {
                int c0 = wn * 64 + nt * 8 + (lid & 3) * 2;
                float bi0 = bs[c0], bi1 = bs[c0 + 1];
                #pragma unroll
                for (int half = 0; half < 2; half++) {
                    int row = wm * 32 + mt * 16 + r_lane + half * 8;
                    float g0 = gelu_exact(acc1[mt][nt][half * 2]     + bi0);
                    float g1 = gelu_exact(acc1[mt][nt][half * 2 + 1] + bi1);
                    __half h0 = __float2half(g0), h1 = __float2half(g1);
                    uint32_t hp = ((uint32_t)__half_as_ushort(h1) << 16) | __half_as_ushort(h0);
                    __half l0 = __float2half(g0 - __half2float(h0));
                    __half l1 = __float2half(g1 - __half2float(h1));
                    uint32_t lp = ((uint32_t)__half_as_ushort(l1) << 16) | __half_as_ushort(l0);
                    *(uint32_t*)(sm + SM_HHI + row * LDB + c0 * 2) = hp;
                    *(uint32_t*)(sm + SM_HHI + TILEB + row * LDB + c0 * 2) = lp;
                }
            }
        }
        CP_WAIT0();
        __syncthreads();

        // ---- GEMM2: [128 tok][128 outc] += H . W2^T over this 128-k chunk ----
        gemm_chunk(smb + SM_HHI, smb + SM_W, acc2, lid, wm, wn);
        __syncthreads();   // before next chunk overwrites W / H
    }

    // ---- final epilogue: weighted atomic scatter ----
    if (tid < 128) bs[tid] = b2[tid];
    __syncthreads();
    #pragma unroll
    for (int mt = 0; mt < 2; mt++) {
        #pragma unroll
        for (int half = 0; half < 2; half++) {
            int t = wm * 32 + mt * 16 + r_lane + half * 8;
            int tok = tk[t];
            float w = tw[t];
            int bb = tok / HHW, s = tok - bb * HHW;
            float* ob = out + (size_t)(bb * CC) * HHW + s;
            #pragma unroll
            for (int nt = 0; nt < 8; nt++) {
                int c0 = wn * 64 + nt * 8 + (lid & 3) * 2;
                atomicAdd(&ob[(size_t)c0 * HHW],
                          w * (acc2[mt][nt][half * 2]     + bs[c0]));
                atomicAdd(&ob[(size_t)(c0 + 1) * HHW],
                          w * (acc2[mt][nt][half * 2 + 1] + bs[c0 + 1]));
            }
        }
    }
}

// ================================================================
extern "C" void kernel_launch(void* const* d_in, const int* in_sizes, int n_in,
                              void* d_out, int out_size) {
    const float* x   = (const float*)d_in[0];
    const float* sw1 = (const float*)d_in[1];
    const float* sb1 = (const float*)d_in[2];
    const float* sw2 = (const float*)d_in[3];
    const float* sb2 = (const float*)d_in[4];
    const float* gw  = (const float*)d_in[5];
    const float* gb  = (const float*)d_in[6];
    const float* ew1 = (const float*)d_in[7];
    const float* eb1 = (const float*)d_in[8];
    const float* ew2 = (const float*)d_in[9];
    const float* eb2 = (const float*)d_in[10];
    float* out = (float*)d_out;

    cudaFuncSetAttribute(moe_mma_kernel,
                         cudaFuncAttributeMaxDynamicSharedMemorySize, SM_TOTAL);

    init_kernel<<<NOUT / 4 / 256, 256>>>(x, out);
    transpose_kernel<<<dim3(HHW / 32, CC / 32, BB), dim3(32, 8)>>>(x);
    convert_w_kernel<<<W1TOT / 256, 256>>>(sw1, ew1, sw2, ew2);
    router_kernel<<<NTOK * 2 / 256, 256>>>(x, gw, gb);
    moe_mma_kernel<<<dim3(NTOK / TMT, EE + 1), 256, SM_TOTAL>>>(sb1, sb2, eb1, eb2, out);
    finalize_kernel<<<1, 32>>>(out, out_size);
}

// round 11
// speedup vs baseline: 1.9112x; 1.2947x over previous
#include <cuda_runtime.h>
#include <cuda_fp16.h>
#include <math.h>
#include <stdint.h>

#define CC    128          // channels
#define HHID  512          // expert hidden dim
#define EE    8            // routed experts
#define BB    8            // batch
#define HHW   9216         // 96*96
#define NTOK  73728        // BB*HHW
#define NOUT  (NTOK*CC)
#define TMT   128          // tokens per tile (GEMM M)
#define NE1   (EE+1)
#define W1TOT (NE1*HHID*CC)

#define LDB   272          // smem row stride in bytes (136 fp16: 128 + 8 pad)
#define TILEB (128*LDB)    // 34816 B per tile

// ---- shared memory layout (bytes); single-precision fp16 everywhere ----
#define SM_TK    0
#define SM_TW    512
#define SM_BIAS  1024
#define SM_A     2048
#define SM_W     (SM_A+TILEB)
#define SM_H     (SM_W+TILEB)
#define SM_TOTAL (SM_H+TILEB)   // 106496 B

// ---- device scratch ----
__device__ __half g_xh[(size_t)NTOK*CC];
__device__ __half g_w1h[W1TOT];
__device__ __half g_w2h[W1TOT];
__device__ int   g_tok[EE*NTOK];
__device__ float g_wt[EE*NTOK];
__device__ int   g_cnt[EE];
__device__ float g_probsum[EE];
__device__ int   g_loadsum[EE];

__device__ __forceinline__ float gelu_exact(float v) {
    return 0.5f * v * (1.0f + erff(v * 0.70710678118654752440f));
}
__device__ __forceinline__ uint32_t smem_u32(const void* p) {
    uint32_t a;
    asm("{ .reg .u64 t; cvta.to.shared.u64 t, %1; cvt.u32.u64 %0, t; }" : "=r"(a) : "l"(p));
    return a;
}
#define CP16(s, g)   asm volatile("cp.async.cg.shared.global [%0], [%1], 16;" :: "r"(s), "l"(g) : "memory")
#define CP_COMMIT()  asm volatile("cp.async.commit_group;" ::: "memory")
#define CP_WAIT0()   asm volatile("cp.async.wait_group 0;" ::: "memory")
#define LDM_X4(r0, r1, r2, r3, a) \
    asm volatile("ldmatrix.sync.aligned.m8n8.x4.shared.b16 {%0,%1,%2,%3}, [%4];" \
        : "=r"(r0), "=r"(r1), "=r"(r2), "=r"(r3) : "r"(a))

__device__ __forceinline__ void mma16816(float* d, const uint32_t* a, const uint32_t* b) {
    asm volatile("mma.sync.aligned.m16n8k16.row.col.f32.f16.f16.f32 "
        "{%0,%1,%2,%3}, {%4,%5,%6,%7}, {%8,%9}, {%0,%1,%2,%3};"
        : "+f"(d[0]), "+f"(d[1]), "+f"(d[2]), "+f"(d[3])
        : "r"(a[0]), "r"(a[1]), "r"(a[2]), "r"(a[3]), "r"(b[0]), "r"(b[1]));
}

// one 128x128x128 GEMM chunk, single-pass fp16.
// acc[mt][nt][4] accumulates [32 tok][64 cols] per warp. Warps 4(m) x 2(n).
__device__ __forceinline__ void gemm_chunk(uint32_t aT, uint32_t wT,
                                           float acc[2][8][4], int lid, int wm, int wn) {
    int a_r  = (lid & 7) + ((lid >> 3) & 1) * 8;
    int a_ko = ((lid >> 4) & 1) * 16;
    int b_n  = (lid & 7) + ((lid >> 4) & 1) * 8;
    int b_ko = ((lid >> 3) & 1) * 16;
    uint32_t aBase = aT + (uint32_t)(wm * 32 + a_r) * LDB + a_ko;
    uint32_t bBase = wT + (uint32_t)(wn * 64 + b_n) * LDB + b_ko;

    #pragma unroll 2
    for (int k0 = 0; k0 < 8; k0++) {
        uint32_t kb = k0 * 32;
        uint32_t ah[2][4];
        #pragma unroll
        for (int mt = 0; mt < 2; mt++) {
            uint32_t ad = aBase + (uint32_t)(mt * 16) * LDB + kb;
            LDM_X4(ah[mt][0], ah[mt][1], ah[mt][2], ah[mt][3], ad);
        }
        #pragma unroll
        for (int ntp = 0; ntp < 4; ntp++) {
            uint32_t bd = bBase + (uint32_t)(ntp * 16) * LDB + kb;
            uint32_t bh[4];
            LDM_X4(bh[0], bh[1], bh[2], bh[3], bd);
            #pragma unroll
            for (int g = 0; g < 2; g++) {
                int nt = ntp * 2 + g;
                #pragma unroll
                for (int mt = 0; mt < 2; mt++)
                    mma16816(acc[mt][nt], ah[mt], bh + 2 * g);
            }
        }
    }
}

// ================================================================ init
__global__ void init_kernel(const float* __restrict__ x, float* __restrict__ out) {
    int i = blockIdx.x * blockDim.x + threadIdx.x;
    ((float4*)out)[i] = ((const float4*)x)[i];
    if (blockIdx.x == 0 && threadIdx.x < EE) {
        g_cnt[threadIdx.x] = 0; g_probsum[threadIdx.x] = 0.f; g_loadsum[threadIdx.x] = 0;
    }
}

// ================================================================ transpose + fp16 convert
__global__ void transpose_kernel(const float* __restrict__ x) {
    __shared__ float t[32][33];
    int b = blockIdx.z, c0 = blockIdx.y * 32, s0 = blockIdx.x * 32;
    int tx = threadIdx.x, ty = threadIdx.y;
    #pragma unroll
    for (int i = 0; i < 4; i++) {
        int c = c0 + ty + i * 8;
        t[ty + i * 8][tx] = x[(size_t)(b * CC + c) * HHW + s0 + tx];
    }
    __syncthreads();
    #pragma unroll
    for (int i = 0; i < 4; i++) {
        int s = s0 + ty + i * 8;
        g_xh[(size_t)(b * HHW + s) * CC + c0 + tx] = __float2half(t[tx][ty + i * 8]);
    }
}

// ================================================================ weight fp16 convert
__global__ void convert_w_kernel(const float* __restrict__ sw1, const float* __restrict__ ew1,
                                 const float* __restrict__ sw2, const float* __restrict__ ew2) {
    int i = blockIdx.x * 256 + threadIdx.x;
    float v1 = (i < EE * HHID * CC) ? ew1[i] : sw1[i - EE * HHID * CC];
    g_w1h[i] = __float2half(v1);
    float v2 = (i < EE * CC * HHID) ? ew2[i] : sw2[i - EE * CC * HHID];
    g_w2h[i] = __float2half(v2);
}

// ================================================================ router (2 threads/token)
__global__ void router_kernel(const float* __restrict__ x,
                              const float* __restrict__ gw,
                              const float* __restrict__ gb) {
    __shared__ float gws[EE * CC];
    __shared__ int   scnt[EE];
    __shared__ float sprob[EE];
    __shared__ int   sbase[EE];
    int tid = threadIdx.x;
    for (int i = tid; i < EE * CC; i += blockDim.x) gws[i] = gw[i];
    if (tid < EE) { scnt[tid] = 0; sprob[tid] = 0.f; }
    __syncthreads();

    int idx = blockIdx.x * 256 + tid;
    int n = idx >> 1, half = idx & 1;
    int b = n / HHW, s = n - b * HHW;
    const float* xb = x + (size_t)b * CC * HHW + s + (size_t)(half * 64) * HHW;
    const float* gwp = gws + half * 64;

    float acc[EE];
    #pragma unroll
    for (int e = 0; e < EE; e++) acc[e] = half ? 0.f : gb[e];
    #pragma unroll 8
    for (int c = 0; c < 64; c++) {
        float xv = __ldg(&xb[(size_t)c * HHW]);
        #pragma unroll
        for (int e = 0; e < EE; e++) acc[e] += xv * gwp[e * CC + c];
    }
    #pragma unroll
    for (int e = 0; e < EE; e++) acc[e] += __shfl_xor_sync(0xffffffffu, acc[e], 1);

    bool active = (half == 0);
    int id[3]; float pv[3]; float winv = 0.f; int slot[3];
    if (active) {
        float m = acc[0];
        #pragma unroll
        for (int e = 1; e < EE; e++) m = fmaxf(m, acc[e]);
        float sum = 0.f;
        #pragma unroll
        for (int e = 0; e < EE; e++) { acc[e] = expf(acc[e] - m); sum += acc[e]; }
        float inv = 1.f / sum;
        #pragma unroll
        for (int e = 0; e < EE; e++) { acc[e] *= inv; atomicAdd(&sprob[e], acc[e]); }
        float tmp[EE];
        #pragma unroll
        for (int e = 0; e < EE; e++) tmp[e] = acc[e];
        float wsum = 0.f;
        #pragma unroll
        for (int k = 0; k < 3; k++) {
            int bi = 0; float bv = tmp[0];
            #pragma unroll
            for (int e = 1; e < EE; e++) if (tmp[e] > bv) { bv = tmp[e]; bi = e; }
            id[k] = bi; pv[k] = bv; tmp[bi] = -1.f; wsum += bv;
        }
        winv = 1.f / wsum;
        #pragma unroll
        for (int k = 0; k < 3; k++) slot[k] = atomicAdd(&scnt[id[k]], 1);
    }
    __syncthreads();
    if (tid < EE) {
        sbase[tid] = atomicAdd(&g_cnt[tid], scnt[tid]);
        atomicAdd(&g_probsum[tid], sprob[tid]);
        atomicAdd(&g_loadsum[tid], scnt[tid]);
    }
    __syncthreads();
    if (active) {
        #pragma unroll
        for (int k = 0; k < 3; k++) {
            int pos = sbase[id[k]] + slot[k];
            g_tok[id[k] * NTOK + pos] = n;
            g_wt[id[k] * NTOK + pos]  = pv[k] * winv;
        }
    }
}

// ================================================================ aux loss
__global__ void finalize_kernel(float* __restrict__ out, int out_size) {
    if (threadIdx.x == 0) {
        float a = 0.f;
        for (int e = 0; e < EE; e++) a += g_probsum[e] * (float)g_loadsum[e];
        out[out_size - 1] = (float)EE * a / ((float)NTOK * (float)NTOK);
    }
}

// ================================================================ fused MoE (HMMA fp16 single-pass)
__global__ __launch_bounds__(256, 1) void moe_mma_kernel(
    const float* __restrict__ sb1, const float* __restrict__ sb2,
    const float* __restrict__ eb1, const float* __restrict__ eb2,
    float* __restrict__ out)
{
    extern __shared__ char sm[];
    uint32_t smb = smem_u32(sm);
    int tid = threadIdx.x, wid = tid >> 5, lid = tid & 31;
    int e = blockIdx.y;

    int count = (e < EE) ? g_cnt[e] : NTOK;
    int t0g = blockIdx.x * TMT;
    if (t0g >= count) return;

    const __half* w1h = g_w1h + (size_t)e * HHID * CC;
    const __half* w2h = g_w2h + (size_t)e * CC * HHID;
    const float* b1 = (e < EE) ? eb1 + e * HHID : sb1;
    const float* b2 = (e < EE) ? eb2 + e * CC   : sb2;

    int*   tk = (int*)(sm + SM_TK);
    float* tw = (float*)(sm + SM_TW);
    float* bs = (float*)(sm + SM_BIAS);

    if (tid < TMT) {
        int idx = t0g + tid;
        if (e < EE) {
            if (idx < count) { tk[tid] = g_tok[e * NTOK + idx]; tw[tid] = g_wt[e * NTOK + idx]; }
            else             { tk[tid] = 0;                     tw[tid] = 0.f; }
        } else { tk[tid] = idx; tw[tid] = 1.f; }
    }
    __syncthreads();

    // gather x rows into A tile via cp.async (256B per token)
    {
        int t = tid >> 1, hf = tid & 1;
        int tok = tk[t];
        const char* src = (const char*)(g_xh + (size_t)tok * CC) + hf * 128;
        uint32_t dst = smb + SM_A + t * LDB + hf * 128;
        #pragma unroll
        for (int i = 0; i < 8; i++) CP16(dst + i * 16, src + i * 16);
    }

    int wm = wid & 3, wn = wid >> 2;
    int r_lane = lid >> 2;
    int stg_n = tid & 127, stg_h = tid >> 7;   // staging: row, 128B half

    float acc2[2][8][4];
    #pragma unroll
    for (int mt = 0; mt < 2; mt++)
        #pragma unroll
        for (int nt = 0; nt < 8; nt++)
            #pragma unroll
            for (int q = 0; q < 4; q++) acc2[mt][nt][q] = 0.f;

    for (int j = 0; j < 4; j++) {
        // ---- stage w1 chunk rows [hid_out][k=C] + bias ----
        {
            const char* src = (const char*)(w1h + (size_t)(j * 128 + stg_n) * CC) + stg_h * 128;
            uint32_t dst = smb + SM_W + stg_n * LDB + stg_h * 128;
            #pragma unroll
            for (int i = 0; i < 8; i++) CP16(dst + i * 16, src + i * 16);
            if (tid < 128) bs[tid] = b1[j * 128 + tid];
        }
        CP_COMMIT(); CP_WAIT0();
        __syncthreads();

        // ---- GEMM1: [128 tok][128 hid] over K=128 ----
        float acc1[2][8][4];
        #pragma unroll
        for (int mt = 0; mt < 2; mt++)
            #pragma unroll
            for (int nt = 0; nt < 8; nt++)
                #pragma unroll
                for (int q = 0; q < 4; q++) acc1[mt][nt][q] = 0.f;
        gemm_chunk(smb + SM_A, smb + SM_W, acc1, lid, wm, wn);
        __syncthreads();   // GEMM1 reads of W done

        // ---- stage w2 chunk [128 outc][k=hid chunk]; epilogue1 -> H ----
        {
            const char* src = (const char*)(w2h + (size_t)stg_n * HHID + j * 128) + stg_h * 128;
            uint32_t dst = smb + SM_W + stg_n * LDB + stg_h * 128;
            #pragma unroll
            for (int i = 0; i < 8; i++) CP16(dst + i * 16, src + i * 16);
        }
        CP_COMMIT();
        #pragma unroll
        for (int mt = 0; mt < 2; mt++) {
            #pragma unroll
            for (int nt = 0; nt < 8; nt++) {
                int c0 = wn * 64 + nt * 8 + (lid & 3) * 2;
                float bi0 = bs[c0], bi1 = bs[c0 + 1];
                #pragma unroll
                for (int half = 0; half < 2; half++) {
                    int row = wm * 32 + mt * 16 + r_lane + half * 8;
                    float g0 = gelu_exact(acc1[mt][nt][half * 2]     + bi0);
                    float g1 = gelu_exact(acc1[mt][nt][half * 2 + 1] + bi1);
                    __half h0 = __float2half(g0), h1 = __float2half(g1);
                    uint32_t hp = ((uint32_t)__half_as_ushort(h1) << 16) | __half_as_ushort(h0);
                    *(uint32_t*)(sm + SM_H + row * LDB + c0 * 2) = hp;
                }
            }
        }
        CP_WAIT0();
        __syncthreads();

        // ---- GEMM2: [128 tok][128 outc] += H . W2^T over this 128-k chunk ----
        gemm_chunk(smb + SM_H, smb + SM_W, acc2, lid, wm, wn);
        __syncthreads();   // before next chunk overwrites W / H
    }

    // ---- final epilogue: weighted atomic scatter ----
    if (tid < 128) bs[tid] = b2[tid];
    __syncthreads();
    #pragma unroll
    for (int mt = 0; mt < 2; mt++) {
        #pragma unroll
        for (int half = 0; half < 2; half++) {
            int t = wm * 32 + mt * 16 + r_lane + half * 8;
            int tok = tk[t];
            float w = tw[t];
            int bb = tok / HHW, s = tok - bb * HHW;
            float* ob = out + (size_t)(bb * CC) * HHW + s;
            #pragma unroll
            for (int nt = 0; nt < 8; nt++) {
                int c0 = wn * 64 + nt * 8 + (lid & 3) * 2;
                atomicAdd(&ob[(size_t)c0 * HHW],
                          w * (acc2[mt][nt][half * 2]     + bs[c0]));
                atomicAdd(&ob[(size_t)(c0 + 1) * HHW],
                          w * (acc2[mt][nt][half * 2 + 1] + bs[c0 + 1]));
            }
        }
    }
}

// ================================================================
extern "C" void kernel_launch(void* const* d_in, const int* in_sizes, int n_in,
                              void* d_out, int out_size) {
    const float* x   = (const float*)d_in[0];
    const float* sw1 = (const float*)d_in[1];
    const float* sb1 = (const float*)d_in[2];
    const float* sw2 = (const float*)d_in[3];
    const float* sb2 = (const float*)d_in[4];
    const float* gw  = (const float*)d_in[5];
    const float* gb  = (const float*)d_in[6];
    const float* ew1 = (const float*)d_in[7];
    const float* eb1 = (const float*)d_in[8];
    const float* ew2 = (const float*)d_in[9];
    const float* eb2 = (const float*)d_in[10];
    float* out = (float*)d_out;

    cudaFuncSetAttribute(moe_mma_kernel,
                         cudaFuncAttributeMaxDynamicSharedMemorySize, SM_TOTAL);

    init_kernel<<<NOUT / 4 / 256, 256>>>(x, out);
    transpose_kernel<<<dim3(HHW / 32, CC / 32, BB), dim3(32, 8)>>>(x);
    convert_w_kernel<<<W1TOT / 256, 256>>>(sw1, ew1, sw2, ew2);
    router_kernel<<<NTOK * 2 / 256, 256>>>(x, gw, gb);
    moe_mma_kernel<<<dim3(NTOK / TMT, EE + 1), 256, SM_TOTAL>>>(sb1, sb2, eb1, eb2, out);
    finalize_kernel<<<1, 32>>>(out, out_size);
}